// round 1
// baseline (speedup 1.0000x reference)
#include <cuda_runtime.h>
#include <cstdint>

#define NMODES 32
#define NLEN   8192
#define NHALF  4096
#define JPAD   4224          // padded j-extent (covers 33 inverse tiles of 128)
#define NROWS  2048          // 32 batch * 64 channels
#define SPLITK 8
#define NCHUNK 257           // ceil(4097/16) forward k-chunks of 16

typedef unsigned long long ull;

// Scratch (device globals; no runtime allocation allowed)
__device__ float2 g_table[NMODES * JPAD];            // (cos, -sin), ~1.1 MB
__device__ float2 g_xpart[SPLITK * NROWS * NMODES];  // forward split-K partials, 4 MB
__device__ float2 g_coef[NROWS * NMODES];            // (c*Re, c*Im) after einsum
__device__ float2 g_wpack[NMODES * 64 * 64];         // weights repacked [m][i][o]

__device__ __forceinline__ ull fma2(ull a, ull b, ull c) {
    ull d;
    asm("fma.rn.f32x2 %0, %1, %2, %3;" : "=l"(d) : "l"(a), "l"(b), "l"(c));
    return d;
}
__device__ __forceinline__ ull ldu(const float2* p) {
    return *reinterpret_cast<const ull*>(p);
}
__device__ __forceinline__ float2 u2f(ull v) {
    float2 f;
    f.x = __uint_as_float((unsigned)v);
    f.y = __uint_as_float((unsigned)(v >> 32));
    return f;
}

// ---------------------------------------------------------------------------
// Kernel 1: trig table  T[m][j] = (cos(2*pi*m*j/N), -sin(...)), j in [0,4096],
// zero-padded to JPAD. Exact int reduction mod 8192 -> sincospif (high accuracy).
// ---------------------------------------------------------------------------
__global__ void init_table_kernel() {
    int idx = blockIdx.x * blockDim.x + threadIdx.x;
    if (idx >= NMODES * JPAD) return;
    int m = idx / JPAD;
    int j = idx - m * JPAD;
    float2 v;
    if (j > NHALF) {
        v = make_float2(0.f, 0.f);
    } else {
        int p = (m * j) & (NLEN - 1);            // theta/pi = p/4096, exact
        float a = (float)p * (1.0f / 4096.0f);
        float s, c;
        sincospif(a, &s, &c);
        v = make_float2(c, -s);
    }
    g_table[idx] = v;
}

// ---------------------------------------------------------------------------
// Kernel 2: forward projection (folded DFT), split-K.
// Block: 64 rows x 32 mode-pairs, thread tile 4 rows x 2 modes, k-chunks of 16.
// acc(Re,Im) += (e,o) * (cos,-sin) as packed f32x2.
// ---------------------------------------------------------------------------
__global__ __launch_bounds__(256) void fwd_kernel(const float* __restrict__ x) {
    __shared__ float2 eos[16 * 66];    // [jj][row], padded stride 66
    __shared__ float2 trigs[16 * 33];  // [jj][m], padded stride 33
    const int rb = blockIdx.x;         // 0..31 row blocks of 64
    const int s  = blockIdx.y;         // split-K slice
    const int t  = threadIdx.x;
    const int tx = t & 15;             // mode-pair group
    const int ty = t >> 4;             // row group
    const int row0 = rb * 64;

    ull acc[4][2];
#pragma unroll
    for (int u = 0; u < 4; u++)
#pragma unroll
        for (int v = 0; v < 2; v++) acc[u][v] = 0ull;

    for (int ch = s; ch < NCHUNK; ch += SPLITK) {
        const int j0 = ch * 16;
        // even/odd fill: e = x[j]+x[N-j], o = x[j]-x[N-j] with edge handling
        {
            int idx0 = t * 4;
            int r   = idx0 >> 4;
            int jjb = idx0 & 15;
            const float* xr = x + (size_t)(row0 + r) * NLEN;
#pragma unroll
            for (int q = 0; q < 4; q++) {
                int jj = jjb + q;
                int j  = j0 + jj;
                float e, o;
                if (j == 0)            { e = xr[0];      o = 0.f; }
                else if (j < NHALF)    { float a = xr[j], b2 = xr[NLEN - j];
                                         e = a + b2;     o = a - b2; }
                else if (j == NHALF)   { e = xr[NHALF];  o = 0.f; }
                else                   { e = 0.f;        o = 0.f; }
                eos[jj * 66 + r] = make_float2(e, o);
            }
        }
        // trig tile fill (coalesced per m-row)
#pragma unroll
        for (int q = 0; q < 2; q++) {
            int idx = t + q * 256;
            int m = idx >> 4, jj = idx & 15;
            trigs[jj * 33 + m] = g_table[m * JPAD + j0 + jj];
        }
        __syncthreads();
#pragma unroll
        for (int jj = 0; jj < 16; jj++) {
            ull tg0 = ldu(&trigs[jj * 33 + tx]);
            ull tg1 = ldu(&trigs[jj * 33 + tx + 16]);
#pragma unroll
            for (int u = 0; u < 4; u++) {
                ull e = ldu(&eos[jj * 66 + ty + 16 * u]);
                acc[u][0] = fma2(e, tg0, acc[u][0]);
                acc[u][1] = fma2(e, tg1, acc[u][1]);
            }
        }
        __syncthreads();
    }
#pragma unroll
    for (int u = 0; u < 4; u++)
#pragma unroll
        for (int v = 0; v < 2; v++)
            g_xpart[((size_t)s * NROWS + row0 + ty + 16 * u) * NMODES + tx + 16 * v]
                = u2f(acc[u][v]);
}

// ---------------------------------------------------------------------------
// Kernel 3: repack weights -> [m][i][o] interleaved (re,im) for coalesced einsum
// ---------------------------------------------------------------------------
__global__ void repack_kernel(const float* __restrict__ wr, const float* __restrict__ wi) {
    int idx = blockIdx.x * blockDim.x + threadIdx.x;
    if (idx >= 64 * 64 * NMODES) return;
    int m = idx & 31;
    int o = (idx >> 5) & 63;
    int i = idx >> 11;
    g_wpack[(m * 64 + i) * 64 + o] = make_float2(wr[idx], wi[idx]);
}

// ---------------------------------------------------------------------------
// Kernel 4: complex einsum over Cin + split-K reduce + irfft scaling
// coef[b,o,m] = c_m * (Sum_i X[b,i,m] * w[i,o,m]),  c_0=1/N, c_m=2/N
// ---------------------------------------------------------------------------
__global__ __launch_bounds__(64) void einsum_kernel() {
    __shared__ float2 Xs[64];
    const int b = blockIdx.x, m = blockIdx.y, o = threadIdx.x;
    float2 s = make_float2(0.f, 0.f);
#pragma unroll
    for (int p = 0; p < SPLITK; p++) {
        float2 v = g_xpart[((size_t)p * NROWS + b * 64 + o) * NMODES + m];
        s.x += v.x; s.y += v.y;
    }
    Xs[o] = s;
    __syncthreads();
    float ar = 0.f, ai = 0.f;
#pragma unroll 8
    for (int i = 0; i < 64; i++) {
        float2 X = Xs[i];
        float2 w = g_wpack[(m * 64 + i) * 64 + o];
        ar = fmaf(X.x, w.x, ar);
        ar = fmaf(-X.y, w.y, ar);
        ai = fmaf(X.x, w.y, ai);
        ai = fmaf(X.y, w.x, ai);
    }
    float c = (m == 0 ? 1.f : 2.f) / (float)NLEN;
    g_coef[(b * 64 + o) * NMODES + m] = make_float2(c * ar, c * ai);
}

// ---------------------------------------------------------------------------
// Kernel 5: inverse (folded irfft). K=32 GEMM:
// (P,Q) += (cA,cB) * (cos,-sin);  out[j] = P+Q, out[N-j] = P-Q.
// Block: 32 rows x 128 j, thread tile 4x4.
// ---------------------------------------------------------------------------
__global__ __launch_bounds__(256) void inv_kernel(float* __restrict__ out) {
    __shared__ float2 coefs[32 * 33];   // [r][m] padded
    __shared__ float2 trigs[32 * 129];  // [m][jj] padded
    const int rb = blockIdx.x, jb = blockIdx.y;
    const int t = threadIdx.x;
    const int tx = t & 31, ty = t >> 5;
    const int row0 = rb * 32, j0 = jb * 128;

#pragma unroll
    for (int q = 0; q < 4; q++) {
        int idx = t * 4 + q;
        int r = idx >> 5, m = idx & 31;
        coefs[r * 33 + m] = g_coef[(row0 + r) * NMODES + m];
    }
#pragma unroll
    for (int q = 0; q < 16; q++) {
        int idx = q * 256 + t;
        int m = idx >> 7, jj = idx & 127;
        trigs[m * 129 + jj] = g_table[m * JPAD + j0 + jj];
    }
    __syncthreads();

    ull acc[4][4];
#pragma unroll
    for (int u = 0; u < 4; u++)
#pragma unroll
        for (int v = 0; v < 4; v++) acc[u][v] = 0ull;

#pragma unroll
    for (int m = 0; m < NMODES; m++) {
        ull g0 = ldu(&trigs[m * 129 + tx]);
        ull g1 = ldu(&trigs[m * 129 + tx + 32]);
        ull g2 = ldu(&trigs[m * 129 + tx + 64]);
        ull g3 = ldu(&trigs[m * 129 + tx + 96]);
#pragma unroll
        for (int u = 0; u < 4; u++) {
            ull c = ldu(&coefs[(ty + 8 * u) * 33 + m]);
            acc[u][0] = fma2(c, g0, acc[u][0]);
            acc[u][1] = fma2(c, g1, acc[u][1]);
            acc[u][2] = fma2(c, g2, acc[u][2]);
            acc[u][3] = fma2(c, g3, acc[u][3]);
        }
    }

#pragma unroll
    for (int u = 0; u < 4; u++) {
        int r = row0 + ty + 8 * u;
        float* orow = out + (size_t)r * NLEN;
#pragma unroll
        for (int v = 0; v < 4; v++) {
            int j = j0 + tx + 32 * v;
            float2 pq = u2f(acc[u][v]);
            if (j <= NHALF)           orow[j] = pq.x + pq.y;           // out[j]   = P+Q
            if (j >= 1 && j < NHALF)  orow[NLEN - j] = pq.x - pq.y;    // out[N-j] = P-Q
        }
    }
}

// ---------------------------------------------------------------------------
extern "C" void kernel_launch(void* const* d_in, const int* in_sizes, int n_in,
                              void* d_out, int out_size) {
    const float* x  = (const float*)d_in[0];
    const float* wr = (const float*)d_in[1];
    const float* wi = (const float*)d_in[2];
    float* out = (float*)d_out;

    init_table_kernel<<<(NMODES * JPAD + 255) / 256, 256>>>();
    fwd_kernel<<<dim3(32, SPLITK), 256>>>(x);
    repack_kernel<<<(64 * 64 * NMODES + 255) / 256, 256>>>(wr, wi);
    einsum_kernel<<<dim3(32, 32), 64>>>();
    inv_kernel<<<dim3(64, 33), 256>>>(out);
}